// round 1
// baseline (speedup 1.0000x reference)
#include <cuda_runtime.h>
#include <math.h>

// Problem constants (fixed by the dataset generator)
#define NN 20000
#define EE 320000
#define RR 100
#define FF 256
#define HH 8
#define DD 32
#define FHID 1024   // 4*F
#define ALPHA 0.1f
#define SLOPE 0.2f

// ------------------------- scratch (device globals) -------------------------
__device__ float g_xln[NN * FF];
__device__ float g_fh [NN * FF];
__device__ float g_ftl[NN * FF];
__device__ float g_fen[NN * FF];
__device__ float g_rln[RR * FF];
__device__ float g_fr [RR * FF];
__device__ int   g_cnt [NN];
__device__ int   g_fill[NN];
__device__ int   g_rowptr[NN + 1];
__device__ int   g_srcs[EE];
__device__ int   g_rids[EE];
__device__ float g_e[EE * HH];
__device__ float g_a[EE * HH];
__device__ float g_fa[NN * FF];
__device__ float g_fb[NN * FF];
__device__ float g_rst[NN * FF];
__device__ float g_y  [NN * FF];
__device__ float g_hid[NN * FHID];

// ------------------------- selectors ----------------------------------------
__device__ __forceinline__ const float* selA(int s) {
    switch (s) {
        case 0: return g_xln;
        case 1: return g_y;
        case 2: return g_hid;
        case 3: return g_rln;
    }
    return nullptr;
}
__device__ __forceinline__ float* selC(int s, float* ext) {
    switch (s) {
        case 0: return g_fh;
        case 1: return g_ftl;
        case 2: return g_fen;
        case 3: return g_fr;
        case 4: return g_hid;
    }
    return ext;
}
__device__ __forceinline__ const float* selFeat(int s) {
    switch (s) {
        case 0: return g_fen;
        case 1: return g_fa;
        case 2: return g_fb;
    }
    return g_rst;
}
__device__ __forceinline__ float* selFeatW(int s) {
    switch (s) {
        case 1: return g_fa;
        case 2: return g_fb;
    }
    return g_rst;
}

// ------------------------- LayerNorm -----------------------------------------
// one block (256 threads) per row; inSel: -1 = external pointer, 0 = g_rst
// outSel: 0 = g_xln, 1 = g_rln, 2 = g_y
__global__ void ln_kernel(const float* __restrict__ extIn, int inSel, int outSel,
                          const float* __restrict__ gam, const float* __restrict__ bet) {
    const float* in = (inSel < 0) ? extIn : g_rst;
    float* out = (outSel == 0) ? g_xln : (outSel == 1 ? g_rln : g_y);
    int row = blockIdx.x;
    int t = threadIdx.x;
    float x = in[row * FF + t];
    float s = x, s2 = x * x;
    #pragma unroll
    for (int o = 16; o; o >>= 1) {
        s  += __shfl_xor_sync(0xffffffffu, s,  o);
        s2 += __shfl_xor_sync(0xffffffffu, s2, o);
    }
    __shared__ float rs[8], rs2[8];
    int w = t >> 5, l = t & 31;
    if (l == 0) { rs[w] = s; rs2[w] = s2; }
    __syncthreads();
    s = 0.f; s2 = 0.f;
    #pragma unroll
    for (int i = 0; i < 8; i++) { s += rs[i]; s2 += rs2[i]; }
    float m = s * (1.0f / FF);
    float var = s2 * (1.0f / FF) - m * m;
    float inv = rsqrtf(var + 1e-5f);
    out[row * FF + t] = (x - m) * inv * gam[t] + bet[t];
}

// ------------------------- SGEMM (fp32, 128x128x8, 256 thr) ------------------
#define BM 128
#define BN 128
#define BK 8
#define TM 8
#define TN 8

// C[M,Nc] = A[M,K] @ B[K,Nc]  (+bias) (relu if mode&1) (+res if resSel)
__global__ __launch_bounds__(256, 2)
void sgemm(int aSel, int cSel, float* __restrict__ extC,
           const float* __restrict__ B, int M, int Nc, int K,
           const float* __restrict__ bias, int resSel, int mode) {
    const float* A = selA(aSel);
    float* C = selC(cSel, extC);
    const float* res = resSel ? g_rst : nullptr;

    __shared__ float As[BK][BM];
    __shared__ float Bs[BK][BN];
    int tid = threadIdx.x;
    int bx = blockIdx.x, by = blockIdx.y;
    int tx = tid & 15, ty = tid >> 4;

    int aRow = tid >> 1;
    int aCol = (tid & 1) * 4;
    int bRow = tid >> 5;
    int bCol = (tid & 31) * 4;

    int gArow = by * BM + aRow;
    bool aValid = gArow < M;
    const float* Aptr = A + (size_t)gArow * K;
    const float* Bptr = B + (size_t)bRow * Nc + bx * BN + bCol;

    float acc[TM][TN];
    #pragma unroll
    for (int i = 0; i < TM; i++)
        #pragma unroll
        for (int j = 0; j < TN; j++) acc[i][j] = 0.f;
    float rm[TM], rn[TN];

    for (int k0 = 0; k0 < K; k0 += BK) {
        float4 av = aValid ? *(const float4*)(Aptr + k0 + aCol) : make_float4(0.f, 0.f, 0.f, 0.f);
        As[aCol + 0][aRow] = av.x;
        As[aCol + 1][aRow] = av.y;
        As[aCol + 2][aRow] = av.z;
        As[aCol + 3][aRow] = av.w;
        float4 bv = *(const float4*)(Bptr + (size_t)k0 * Nc);
        *(float4*)&Bs[bRow][bCol] = bv;
        __syncthreads();
        #pragma unroll
        for (int kk = 0; kk < BK; kk++) {
            #pragma unroll
            for (int i = 0; i < TM; i++) rm[i] = As[kk][ty * TM + i];
            #pragma unroll
            for (int j = 0; j < TN; j++) rn[j] = Bs[kk][tx * TN + j];
            #pragma unroll
            for (int i = 0; i < TM; i++)
                #pragma unroll
                for (int j = 0; j < TN; j++) acc[i][j] += rm[i] * rn[j];
        }
        __syncthreads();
    }

    #pragma unroll
    for (int i = 0; i < TM; i++) {
        int row = by * BM + ty * TM + i;
        if (row < M) {
            #pragma unroll
            for (int j = 0; j < TN; j++) {
                int col = bx * BN + tx * TN + j;
                float v = acc[i][j];
                if (bias) v += bias[col];
                if (mode & 1) v = fmaxf(v, 0.f);
                if (res) v += res[(size_t)row * Nc + col];
                C[(size_t)row * Nc + col] = v;
            }
        }
    }
}

// ------------------------- CSR build -----------------------------------------
__global__ void zero_kernel() {
    int i = blockIdx.x * blockDim.x + threadIdx.x;
    if (i < NN) { g_cnt[i] = 0; g_fill[i] = 0; }
}

__global__ void count_kernel(const int* __restrict__ dst) {
    int i = blockIdx.x * blockDim.x + threadIdx.x;
    if (i < EE) atomicAdd(&g_cnt[dst[i]], 1);
}

__global__ void scan_kernel() {
    __shared__ int ss[1024];
    int t = threadIdx.x;
    const int CH = (NN + 1023) / 1024;
    int base = t * CH;
    int loc = 0;
    for (int i = 0; i < CH; i++) {
        int idx = base + i;
        if (idx < NN) loc += g_cnt[idx];
    }
    ss[t] = loc;
    __syncthreads();
    for (int off = 1; off < 1024; off <<= 1) {
        int v = (t >= off) ? ss[t - off] : 0;
        __syncthreads();
        ss[t] += v;
        __syncthreads();
    }
    int run = (t == 0) ? 0 : ss[t - 1];
    for (int i = 0; i < CH; i++) {
        int idx = base + i;
        if (idx < NN) { g_rowptr[idx] = run; run += g_cnt[idx]; }
    }
    if (t == 0) g_rowptr[NN] = EE;
}

__global__ void scatter_kernel(const int* __restrict__ src, const int* __restrict__ dst,
                               const int* __restrict__ rid) {
    int i = blockIdx.x * blockDim.x + threadIdx.x;
    if (i < EE) {
        int d = dst[i];
        int pos = g_rowptr[d] + atomicAdd(&g_fill[d], 1);
        g_srcs[pos] = src[i];
        g_rids[pos] = rid[i];
    }
}

// ------------------------- edge attention + softmax ---------------------------
// one warp per dst node
__global__ void attn_kernel(const float* __restrict__ attn) {
    int w = (blockIdx.x * blockDim.x + threadIdx.x) >> 5;
    int lane = threadIdx.x & 31;
    if (w >= NN) return;
    int node = w;
    float tl[HH], av[HH];
    #pragma unroll
    for (int h = 0; h < HH; h++) {
        tl[h] = g_ftl[node * FF + h * DD + lane];
        av[h] = attn[h * DD + lane];
    }
    int beg = g_rowptr[node], end = g_rowptr[node + 1];
    float scale = logf((float)(end - beg)) * (1.0f / DD);
    for (int p = beg; p < end; p++) {
        int s = g_srcs[p], r = g_rids[p];
        #pragma unroll
        for (int h = 0; h < HH; h++) {
            float x = g_fh[s * FF + h * DD + lane] * tl[h] * g_fr[r * FF + h * DD + lane];
            x = (x > 0.f) ? x : SLOPE * x;
            float v = x * av[h];
            #pragma unroll
            for (int o = 16; o; o >>= 1) v += __shfl_xor_sync(0xffffffffu, v, o);
            if (lane == 0) g_e[p * HH + h] = v * scale;
        }
    }
    __syncwarp();
    if (lane < HH) {
        int h = lane;
        float m = -1e30f;
        for (int p = beg; p < end; p++) m = fmaxf(m, g_e[p * HH + h]);
        float ssum = 0.f;
        for (int p = beg; p < end; p++) ssum += expf(g_e[p * HH + h] - m);
        float inv = 1.0f / ssum;
        for (int p = beg; p < end; p++) g_a[p * HH + h] = expf(g_e[p * HH + h] - m) * inv;
    }
}

// ------------------------- diffusion hop --------------------------------------
// one warp per dst node. fout = (1-a)*agg + a*fen  [+ ent_feat on last hop]
__global__ void hop_kernel(int finSel, int foutSel, const float* __restrict__ ent) {
    int w = (blockIdx.x * blockDim.x + threadIdx.x) >> 5;
    int lane = threadIdx.x & 31;
    if (w >= NN) return;
    const float* fin = selFeat(finSel);
    float* fout = selFeatW(foutSel);
    int node = w;
    int beg = g_rowptr[node], end = g_rowptr[node + 1];
    float acc[HH];
    #pragma unroll
    for (int h = 0; h < HH; h++) acc[h] = 0.f;
    for (int p = beg; p < end; p++) {
        int s = g_srcs[p];
        #pragma unroll
        for (int h = 0; h < HH; h++)
            acc[h] += g_a[p * HH + h] * fin[s * FF + h * DD + lane];
    }
    #pragma unroll
    for (int h = 0; h < HH; h++) {
        int idx = node * FF + h * DD + lane;
        float v = (1.0f - ALPHA) * acc[h] + ALPHA * g_fen[idx];
        if (ent) v += ent[idx];
        fout[idx] = v;
    }
}

// ------------------------- launcher -------------------------------------------
extern "C" void kernel_launch(void* const* d_in, const int* in_sizes, int n_in,
                              void* d_out, int out_size) {
    const float* ent_feat = (const float*)d_in[0];
    const float* rel_feat = (const float*)d_in[1];
    const float* W_head   = (const float*)d_in[2];
    const float* W_tail   = (const float*)d_in[3];
    const float* W_ent    = (const float*)d_in[4];
    const float* W_rel    = (const float*)d_in[5];
    const float* attn     = (const float*)d_in[6];
    const float* ln_ent_g = (const float*)d_in[7];
    const float* ln_ent_b = (const float*)d_in[8];
    const float* ln_rel_g = (const float*)d_in[9];
    const float* ln_rel_b = (const float*)d_in[10];
    const float* ln_ff_g  = (const float*)d_in[11];
    const float* ln_ff_b  = (const float*)d_in[12];
    const float* W1       = (const float*)d_in[13];
    const float* b1       = (const float*)d_in[14];
    const float* W2       = (const float*)d_in[15];
    const float* b2       = (const float*)d_in[16];
    const int*   src      = (const int*)d_in[17];
    const int*   dst      = (const int*)d_in[18];
    const int*   rid      = (const int*)d_in[19];
    float* out = (float*)d_out;

    // 1) LayerNorms of inputs
    ln_kernel<<<NN, 256>>>(ent_feat, -1, 0, ln_ent_g, ln_ent_b);   // g_xln
    ln_kernel<<<RR, 256>>>(rel_feat, -1, 1, ln_rel_g, ln_rel_b);   // g_rln

    // 2) Projections
    dim3 gRel(FF / BN, (RR + BM - 1) / BM);
    sgemm<<<gRel, 256>>>(3, 3, nullptr, W_rel, RR, FF, FF, nullptr, 0, 0);   // g_fr
    dim3 gProj(FF / BN, (NN + BM - 1) / BM);
    sgemm<<<gProj, 256>>>(0, 0, nullptr, W_head, NN, FF, FF, nullptr, 0, 0); // g_fh
    sgemm<<<gProj, 256>>>(0, 1, nullptr, W_tail, NN, FF, FF, nullptr, 0, 0); // g_ftl
    sgemm<<<gProj, 256>>>(0, 2, nullptr, W_ent,  NN, FF, FF, nullptr, 0, 0); // g_fen

    // 3) CSR build (sorted by dst)
    zero_kernel<<<(NN + 255) / 256, 256>>>();
    count_kernel<<<(EE + 255) / 256, 256>>>(dst);
    scan_kernel<<<1, 1024>>>();
    scatter_kernel<<<(EE + 255) / 256, 256>>>(src, dst, rid);

    // 4) edge attention scores + per-node softmax
    attn_kernel<<<NN / 8, 256>>>(attn);

    // 5) 5 PPR hops (ping-pong), last hop adds ent_feat residual -> g_rst
    hop_kernel<<<NN / 8, 256>>>(0, 1, nullptr);        // fen  -> fa
    hop_kernel<<<NN / 8, 256>>>(1, 2, nullptr);        // fa   -> fb
    hop_kernel<<<NN / 8, 256>>>(2, 1, nullptr);        // fb   -> fa
    hop_kernel<<<NN / 8, 256>>>(1, 2, nullptr);        // fa   -> fb
    hop_kernel<<<NN / 8, 256>>>(2, 3, ent_feat);       // fb   -> rst (+ent)

    // 6) FFN with pre-LN and residual
    ln_kernel<<<NN, 256>>>(nullptr, 0, 2, ln_ff_g, ln_ff_b);       // g_y = LN(rst)
    dim3 gF1(FHID / BN, (NN + BM - 1) / BM);
    sgemm<<<gF1, 256>>>(1, 4, nullptr, W1, NN, FHID, FF, b1, 0, 1);     // g_hid = relu(y@W1+b1)
    dim3 gF2(FF / BN, (NN + BM - 1) / BM);
    sgemm<<<gF2, 256>>>(2, 5, out, W2, NN, FF, FHID, b2, 1, 0);         // out = hid@W2+b2+rst
}

// round 3
// speedup vs baseline: 3.0488x; 3.0488x over previous
#include <cuda_runtime.h>
#include <math.h>
#include <stdint.h>

// Problem constants
#define NN 20000
#define EE 320000
#define RR 100
#define FF 256
#define HH 8
#define DD 32
#define FHID 1024
#define ALPHA 0.1f
#define SLOPE 0.2f

// ---------------------------------------------------------------------------
__device__ __forceinline__ uint32_t smem_u32(const void* p) {
    uint32_t a;
    asm("{ .reg .u64 t; cvta.to.shared.u64 t, %1; cvt.u32.u64 %0, t; }" : "=r"(a) : "l"(p));
    return a;
}
#define CP_ASYNC16(dst, src) \
    asm volatile("cp.async.cg.shared.global [%0], [%1], 16;" :: "r"(dst), "l"(src) : "memory")
#define CP_COMMIT() asm volatile("cp.async.commit_group;" ::: "memory")
#define CP_WAIT(n)  asm volatile("cp.async.wait_group %0;" :: "n"(n) : "memory")

#define LDSM_X4(r0, r1, r2, r3, addr) \
    asm volatile("ldmatrix.sync.aligned.m8n8.x4.shared.b16 {%0,%1,%2,%3}, [%4];" \
                 : "=r"(r0), "=r"(r1), "=r"(r2), "=r"(r3) : "r"(addr))
#define LDSM_X2(r0, r1, addr) \
    asm volatile("ldmatrix.sync.aligned.m8n8.x2.shared.b16 {%0,%1}, [%2];" \
                 : "=r"(r0), "=r"(r1) : "r"(addr))
#define MMA_TF32(c, a, b) \
    asm volatile("mma.sync.aligned.m16n8k8.row.col.f32.tf32.tf32.f32 " \
                 "{%0,%1,%2,%3},{%4,%5,%6,%7},{%8,%9},{%0,%1,%2,%3};" \
                 : "+f"((c)[0]), "+f"((c)[1]), "+f"((c)[2]), "+f"((c)[3]) \
                 : "r"((a)[0]), "r"((a)[1]), "r"((a)[2]), "r"((a)[3]), \
                   "r"((b)[0]), "r"((b)[1]))

__device__ __forceinline__ float tf32_rnd(float x) {
    uint32_t u = __float_as_uint(x), o;
    asm("cvt.rna.tf32.f32 %0, %1;" : "=r"(o) : "r"(u));
    return __uint_as_float(o);
}

// ------------------------- scratch (device globals) -------------------------
__device__ float g_xln[NN * FF];
__device__ float g_fh [NN * FF];
__device__ float g_ftl[NN * FF];
__device__ float g_fen[NN * FF];
__device__ float g_rln[RR * FF];
__device__ float g_fr [RR * FF];
__device__ int   g_cnt [NN];
__device__ int   g_fill[NN];
__device__ int   g_rowptr[NN + 1];
__device__ int   g_srcs[EE];
__device__ int   g_rids[EE];
__device__ float g_e[EE * HH];
__device__ float g_a[EE * HH];
__device__ float g_fa[NN * FF];
__device__ float g_fb[NN * FF];
__device__ float g_rst[NN * FF];
__device__ float g_y  [NN * FF];
__device__ float g_hid[NN * FHID];
// transposed (K-major) tf32-rounded weights
__device__ float g_wheadT[FF * FF];
__device__ float g_wtailT[FF * FF];
__device__ float g_wentT [FF * FF];
__device__ float g_wrelT [FF * FF];
__device__ float g_w1T[FHID * FF];
__device__ float g_w2T[FF * FHID];

// ------------------------- selectors ----------------------------------------
__device__ __forceinline__ const float* selA(int s) {
    switch (s) {
        case 0: return g_xln;
        case 1: return g_y;
        case 2: return g_hid;
        case 3: return g_rln;
    }
    return nullptr;
}
__device__ __forceinline__ float* selC(int s, float* ext) {
    switch (s) {
        case 0: return g_fh;
        case 1: return g_ftl;
        case 2: return g_fen;
        case 3: return g_fr;
        case 4: return g_hid;
    }
    return ext;
}
__device__ __forceinline__ const float* selFeat(int s) {
    switch (s) {
        case 0: return g_fen;
        case 1: return g_fa;
        case 2: return g_fb;
    }
    return g_rst;
}
__device__ __forceinline__ float* selFeatW(int s) {
    switch (s) {
        case 1: return g_fa;
        case 2: return g_fb;
    }
    return g_rst;
}

// ------------------------- LayerNorm (outputs tf32-rounded) -------------------
__global__ void ln_kernel(const float* __restrict__ extIn, int inSel, int outSel,
                          const float* __restrict__ gam, const float* __restrict__ bet) {
    const float* in = (inSel < 0) ? extIn : g_rst;
    float* out = (outSel == 0) ? g_xln : (outSel == 1 ? g_rln : g_y);
    int row = blockIdx.x;
    int t = threadIdx.x;
    float x = in[row * FF + t];
    float s = x, s2 = x * x;
    #pragma unroll
    for (int o = 16; o; o >>= 1) {
        s  += __shfl_xor_sync(0xffffffffu, s,  o);
        s2 += __shfl_xor_sync(0xffffffffu, s2, o);
    }
    __shared__ float rs[8], rs2[8];
    int w = t >> 5, l = t & 31;
    if (l == 0) { rs[w] = s; rs2[w] = s2; }
    __syncthreads();
    s = 0.f; s2 = 0.f;
    #pragma unroll
    for (int i = 0; i < 8; i++) { s += rs[i]; s2 += rs2[i]; }
    float m = s * (1.0f / FF);
    float var = s2 * (1.0f / FF) - m * m;
    float inv = rsqrtf(var + 1e-5f);
    out[row * FF + t] = tf32_rnd((x - m) * inv * gam[t] + bet[t]);
}

// ------------------------- weight transpose (+tf32 round) --------------------
// B is (K x N) row-major; BT is (N x K) row-major.
__global__ void transpose_rnd(const float* __restrict__ B, float* __restrict__ BT,
                              int K, int N) {
    __shared__ float t[32][33];
    int n0 = blockIdx.x * 32, k0 = blockIdx.y * 32;
    int x = threadIdx.x, y = threadIdx.y;
    #pragma unroll
    for (int r = 0; r < 32; r += 8)
        t[y + r][x] = B[(size_t)(k0 + y + r) * N + n0 + x];
    __syncthreads();
    #pragma unroll
    for (int r = 0; r < 32; r += 8)
        BT[(size_t)(n0 + y + r) * K + k0 + x] = tf32_rnd(t[x][y + r]);
}

// ------------------------- tf32 mma.sync GEMM --------------------------------
// C[M,Nc] = A[M,K] @ BT[Nc,K]^T (+bias) (relu if mode&1) (tf32-round if mode&2)
// (+g_rst residual if resSel)
// 128x128 block tile, BK=32, 8 warps (2x4), warp tile 64x32, double buffered.
#define GSMEM_BYTES 65536   // 2 stages x (A 16KB + B 16KB)

__global__ void __launch_bounds__(256, 1)
mma_gemm(int aSel, const float* __restrict__ BT, int cSel, float* __restrict__ extC,
         int M, int Nc, int K, const float* __restrict__ bias, int resSel, int mode) {
    extern __shared__ float smemf[];
    const uint32_t sb = smem_u32(smemf);
    const float* A = selA(aSel);
    float* C = selC(cSel, extC);
    const float* res = resSel ? g_rst : nullptr;

    const int m0 = blockIdx.y * 128;
    const int n0 = blockIdx.x * 128;
    const int tid = threadIdx.x;
    const int warp = tid >> 5, lane = tid & 31;
    const int wm = warp >> 2, wn = warp & 3;          // 2 x 4 warps

    // ---- async load setup: each thread owns half a 128B row of A and B ----
    const int lrow = tid >> 1, lhalf = tid & 1;
    int aRow = m0 + lrow; if (aRow >= M) aRow = M - 1;
    const float* aG = A + (size_t)aRow * K + lhalf * 16;
    const float* bG = BT + (size_t)(n0 + lrow) * K + lhalf * 16;
    const uint32_t sA = sb + (uint32_t)lrow * 128;
    const uint32_t sB = sb + 16384 + (uint32_t)lrow * 128;
    uint32_t swz[4];
    #pragma unroll
    for (int j = 0; j < 4; j++)
        swz[j] = (uint32_t)(((lhalf * 4 + j) ^ (lrow & 7)) << 4);

    const int nCh = K >> 5;

    float c[4][4][4];
    #pragma unroll
    for (int mt = 0; mt < 4; mt++)
        #pragma unroll
        for (int nt = 0; nt < 4; nt++)
            #pragma unroll
            for (int q = 0; q < 4; q++) c[mt][nt][q] = 0.f;

    // prologue load stage 0
    {
        #pragma unroll
        for (int j = 0; j < 4; j++) CP_ASYNC16(sA + swz[j], aG + j * 4);
        #pragma unroll
        for (int j = 0; j < 4; j++) CP_ASYNC16(sB + swz[j], bG + j * 4);
        CP_COMMIT();
    }

    const int q8 = lane >> 3, r8 = lane & 7;

    for (int i = 0; i < nCh; i++) {
        if (i + 1 < nCh) {
            const uint32_t off = (uint32_t)((i + 1) & 1) * 32768;
            const float* ag = aG + (i + 1) * 32;
            const float* bg = bG + (i + 1) * 32;
            #pragma unroll
            for (int j = 0; j < 4; j++) CP_ASYNC16(sA + off + swz[j], ag + j * 4);
            #pragma unroll
            for (int j = 0; j < 4; j++) CP_ASYNC16(sB + off + swz[j], bg + j * 4);
            CP_COMMIT();
            CP_WAIT(1);
        } else {
            CP_WAIT(0);
        }
        __syncthreads();

        const uint32_t Ab = sb + (uint32_t)(i & 1) * 32768;
        const uint32_t Bb = Ab + 16384;
        #pragma unroll
        for (int ks = 0; ks < 4; ks++) {
            uint32_t a[4][4];
            #pragma unroll
            for (int mt = 0; mt < 4; mt++) {
                const int rl = wm * 64 + mt * 16 + (q8 & 1) * 8 + r8;
                const int kc = ks * 2 + (q8 >> 1);
                const uint32_t ad = Ab + (uint32_t)rl * 128 + (uint32_t)((kc ^ (rl & 7)) << 4);
                LDSM_X4(a[mt][0], a[mt][1], a[mt][2], a[mt][3], ad);
            }
            uint32_t b[4][2];
            #pragma unroll
            for (int nt = 0; nt < 4; nt++) {
                const int nl = wn * 32 + nt * 8 + r8;
                const int kc = ks * 2 + (q8 & 1);
                const uint32_t bd = Bb + (uint32_t)nl * 128 + (uint32_t)((kc ^ (nl & 7)) << 4);
                LDSM_X2(b[nt][0], b[nt][1], bd);
            }
            #pragma unroll
            for (int mt = 0; mt < 4; mt++)
                #pragma unroll
                for (int nt = 0; nt < 4; nt++)
                    MMA_TF32(c[mt][nt], a[mt], b[nt]);
        }
        __syncthreads();
    }

    // ---- epilogue ----
    const int g = lane >> 2, t4 = lane & 3;
    #pragma unroll
    for (int mt = 0; mt < 4; mt++) {
        #pragma unroll
        for (int half = 0; half < 2; half++) {
            const int m = m0 + wm * 64 + mt * 16 + g + half * 8;
            if (m < M) {
                float* cRow = C + (size_t)m * Nc + n0 + wn * 32;
                const float* rRow = res ? (res + (size_t)m * Nc + n0 + wn * 32) : nullptr;
                #pragma unroll
                for (int nt = 0; nt < 4; nt++) {
                    const int colb = nt * 8 + 2 * t4;
                    float v0 = c[mt][nt][half * 2 + 0];
                    float v1 = c[mt][nt][half * 2 + 1];
                    if (bias) {
                        const float* bp = bias + n0 + wn * 32 + colb;
                        v0 += bp[0]; v1 += bp[1];
                    }
                    if (mode & 1) { v0 = fmaxf(v0, 0.f); v1 = fmaxf(v1, 0.f); }
                    if (mode & 2) { v0 = tf32_rnd(v0); v1 = tf32_rnd(v1); }
                    if (rRow) { v0 += rRow[colb]; v1 += rRow[colb + 1]; }
                    float2 v; v.x = v0; v.y = v1;
                    *(float2*)(cRow + colb) = v;
                }
            }
        }
    }
}

// ------------------------- CSR build -----------------------------------------
__global__ void zero_kernel() {
    int i = blockIdx.x * blockDim.x + threadIdx.x;
    if (i < NN) { g_cnt[i] = 0; g_fill[i] = 0; }
}
__global__ void count_kernel(const int* __restrict__ dst) {
    int i = blockIdx.x * blockDim.x + threadIdx.x;
    if (i < EE) atomicAdd(&g_cnt[dst[i]], 1);
}
__global__ void scan_kernel() {
    __shared__ int ss[1024];
    int t = threadIdx.x;
    const int CH = (NN + 1023) / 1024;
    int base = t * CH;
    int loc = 0;
    for (int i = 0; i < CH; i++) {
        int idx = base + i;
        if (idx < NN) loc += g_cnt[idx];
    }
    ss[t] = loc;
    __syncthreads();
    for (int off = 1; off < 1024; off <<= 1) {
        int v = (t >= off) ? ss[t - off] : 0;
        __syncthreads();
        ss[t] += v;
        __syncthreads();
    }
    int run = (t == 0) ? 0 : ss[t - 1];
    for (int i = 0; i < CH; i++) {
        int idx = base + i;
        if (idx < NN) { g_rowptr[idx] = run; run += g_cnt[idx]; }
    }
    if (t == 0) g_rowptr[NN] = EE;
}
__global__ void scatter_kernel(const int* __restrict__ src, const int* __restrict__ dst,
                               const int* __restrict__ rid) {
    int i = blockIdx.x * blockDim.x + threadIdx.x;
    if (i < EE) {
        int d = dst[i];
        int pos = g_rowptr[d] + atomicAdd(&g_fill[d], 1);
        g_srcs[pos] = src[i];
        g_rids[pos] = rid[i];
    }
}

// ------------------------- edge attention + softmax ---------------------------
__global__ void attn_kernel(const float* __restrict__ attn) {
    int w = (blockIdx.x * blockDim.x + threadIdx.x) >> 5;
    int lane = threadIdx.x & 31;
    if (w >= NN) return;
    int node = w;
    float tl[HH], av[HH];
    #pragma unroll
    for (int h = 0; h < HH; h++) {
        tl[h] = g_ftl[node * FF + h * DD + lane];
        av[h] = attn[h * DD + lane];
    }
    int beg = g_rowptr[node], end = g_rowptr[node + 1];
    float scale = logf((float)(end - beg)) * (1.0f / DD);
    for (int p = beg; p < end; p++) {
        int s = g_srcs[p], r = g_rids[p];
        #pragma unroll
        for (int h = 0; h < HH; h++) {
            float x = g_fh[s * FF + h * DD + lane] * tl[h] * g_fr[r * FF + h * DD + lane];
            x = (x > 0.f) ? x : SLOPE * x;
            float v = x * av[h];
            #pragma unroll
            for (int o = 16; o; o >>= 1) v += __shfl_xor_sync(0xffffffffu, v, o);
            if (lane == 0) g_e[p * HH + h] = v * scale;
        }
    }
    __syncwarp();
    if (lane < HH) {
        int h = lane;
        float m = -1e30f;
        for (int p = beg; p < end; p++) m = fmaxf(m, g_e[p * HH + h]);
        float ssum = 0.f;
        for (int p = beg; p < end; p++) ssum += expf(g_e[p * HH + h] - m);
        float inv = 1.0f / ssum;
        for (int p = beg; p < end; p++) g_a[p * HH + h] = expf(g_e[p * HH + h] - m) * inv;
    }
}

// ------------------------- diffusion hop --------------------------------------
__global__ void hop_kernel(int finSel, int foutSel, const float* __restrict__ ent) {
    int w = (blockIdx.x * blockDim.x + threadIdx.x) >> 5;
    int lane = threadIdx.x & 31;
    if (w >= NN) return;
    const float* fin = selFeat(finSel);
    float* fout = selFeatW(foutSel);
    int node = w;
    int beg = g_rowptr[node], end = g_rowptr[node + 1];
    float acc[HH];
    #pragma unroll
    for (int h = 0; h < HH; h++) acc[h] = 0.f;
    for (int p = beg; p < end; p++) {
        int s = g_srcs[p];
        #pragma unroll
        for (int h = 0; h < HH; h++)
            acc[h] += g_a[p * HH + h] * fin[s * FF + h * DD + lane];
    }
    #pragma unroll
    for (int h = 0; h < HH; h++) {
        int idx = node * FF + h * DD + lane;
        float v = (1.0f - ALPHA) * acc[h] + ALPHA * g_fen[idx];
        if (ent) v += ent[idx];
        fout[idx] = v;
    }
}

// ------------------------- launcher -------------------------------------------
extern "C" void kernel_launch(void* const* d_in, const int* in_sizes, int n_in,
                              void* d_out, int out_size) {
    const float* ent_feat = (const float*)d_in[0];
    const float* rel_feat = (const float*)d_in[1];
    const float* W_head   = (const float*)d_in[2];
    const float* W_tail   = (const float*)d_in[3];
    const float* W_ent    = (const float*)d_in[4];
    const float* W_rel    = (const float*)d_in[5];
    const float* attn     = (const float*)d_in[6];
    const float* ln_ent_g = (const float*)d_in[7];
    const float* ln_ent_b = (const float*)d_in[8];
    const float* ln_rel_g = (const float*)d_in[9];
    const float* ln_rel_b = (const float*)d_in[10];
    const float* ln_ff_g  = (const float*)d_in[11];
    const float* ln_ff_b  = (const float*)d_in[12];
    const float* W1       = (const float*)d_in[13];
    const float* b1       = (const float*)d_in[14];
    const float* W2       = (const float*)d_in[15];
    const float* b2       = (const float*)d_in[16];
    const int*   src      = (const int*)d_in[17];
    const int*   dst      = (const int*)d_in[18];
    const int*   rid      = (const int*)d_in[19];
    float* out = (float*)d_out;

    cudaFuncSetAttribute(mma_gemm, cudaFuncAttributeMaxDynamicSharedMemorySize, GSMEM_BYTES);

    // 0) transpose + tf32-round weights (K-major for mma.sync B operand)
    float* whT; cudaGetSymbolAddress((void**)&whT, g_wheadT);
    float* wtT; cudaGetSymbolAddress((void**)&wtT, g_wtailT);
    float* weT; cudaGetSymbolAddress((void**)&weT, g_wentT);
    float* wrT; cudaGetSymbolAddress((void**)&wrT, g_wrelT);
    float* w1T; cudaGetSymbolAddress((void**)&w1T, g_w1T);
    float* w2T; cudaGetSymbolAddress((void**)&w2T, g_w2T);
    dim3 tb(32, 8);
    transpose_rnd<<<dim3(FF / 32, FF / 32), tb>>>(W_head, whT, FF, FF);
    transpose_rnd<<<dim3(FF / 32, FF / 32), tb>>>(W_tail, wtT, FF, FF);
    transpose_rnd<<<dim3(FF / 32, FF / 32), tb>>>(W_ent,  weT, FF, FF);
    transpose_rnd<<<dim3(FF / 32, FF / 32), tb>>>(W_rel,  wrT, FF, FF);
    transpose_rnd<<<dim3(FHID / 32, FF / 32), tb>>>(W1, w1T, FF, FHID);
    transpose_rnd<<<dim3(FF / 32, FHID / 32), tb>>>(W2, w2T, FHID, FF);

    // 1) LayerNorms (outputs tf32-rounded; only consumed by GEMMs)
    ln_kernel<<<NN, 256>>>(ent_feat, -1, 0, ln_ent_g, ln_ent_b);   // g_xln
    ln_kernel<<<RR, 256>>>(rel_feat, -1, 1, ln_rel_g, ln_rel_b);   // g_rln

    // 2) Projections (tf32 mma.sync)
    const int mT = (NN + 127) / 128;   // 157
    mma_gemm<<<dim3(FF / 128, 1), 256, GSMEM_BYTES>>>(3, wrT, 3, nullptr, RR, FF, FF, nullptr, 0, 0);
    mma_gemm<<<dim3(FF / 128, mT), 256, GSMEM_BYTES>>>(0, whT, 0, nullptr, NN, FF, FF, nullptr, 0, 0);
    mma_gemm<<<dim3(FF / 128, mT), 256, GSMEM_BYTES>>>(0, wtT, 1, nullptr, NN, FF, FF, nullptr, 0, 0);
    mma_gemm<<<dim3(FF / 128, mT), 256, GSMEM_BYTES>>>(0, weT, 2, nullptr, NN, FF, FF, nullptr, 0, 0);

    // 3) CSR build (sorted by dst)
    zero_kernel<<<(NN + 255) / 256, 256>>>();
    count_kernel<<<(EE + 255) / 256, 256>>>(dst);
    scan_kernel<<<1, 1024>>>();
    scatter_kernel<<<(EE + 255) / 256, 256>>>(src, dst, rid);

    // 4) edge attention + per-node softmax
    attn_kernel<<<NN / 8, 256>>>(attn);

    // 5) 5 PPR hops (ping-pong), last adds ent_feat residual -> g_rst
    hop_kernel<<<NN / 8, 256>>>(0, 1, nullptr);
    hop_kernel<<<NN / 8, 256>>>(1, 2, nullptr);
    hop_kernel<<<NN / 8, 256>>>(2, 1, nullptr);
    hop_kernel<<<NN / 8, 256>>>(1, 2, nullptr);
    hop_kernel<<<NN / 8, 256>>>(2, 3, ent_feat);

    // 6) FFN with pre-LN and residual
    ln_kernel<<<NN, 256>>>(nullptr, 0, 2, ln_ff_g, ln_ff_b);       // g_y (tf32-rounded)
    mma_gemm<<<dim3(FHID / 128, mT), 256, GSMEM_BYTES>>>(1, w1T, 4, nullptr, NN, FHID, FF, b1, 0, 1 | 2);
    mma_gemm<<<dim3(FF / 128, mT), 256, GSMEM_BYTES>>>(2, w2T, 5, out, NN, FF, FHID, b2, 1, 0);
}

// round 4
// speedup vs baseline: 3.4768x; 1.1404x over previous
#include <cuda_runtime.h>
#include <math.h>
#include <stdint.h>

// Problem constants
#define NN 20000
#define EE 320000
#define RR 100
#define FF 256
#define HH 8
#define DD 32
#define FHID 1024
#define PF 768            // packed projection stride (fh|ftl|fen)
#define ALPHA 0.1f
#define SLOPE 0.2f

// ---------------------------------------------------------------------------
__device__ __forceinline__ uint32_t smem_u32(const void* p) {
    uint32_t a;
    asm("{ .reg .u64 t; cvta.to.shared.u64 t, %1; cvt.u32.u64 %0, t; }" : "=r"(a) : "l"(p));
    return a;
}
#define CP_ASYNC16(dst, src) \
    asm volatile("cp.async.cg.shared.global [%0], [%1], 16;" :: "r"(dst), "l"(src) : "memory")
#define CP_COMMIT() asm volatile("cp.async.commit_group;" ::: "memory")
#define CP_WAIT(n)  asm volatile("cp.async.wait_group %0;" :: "n"(n) : "memory")

#define LDSM_X4(r0, r1, r2, r3, addr) \
    asm volatile("ldmatrix.sync.aligned.m8n8.x4.shared.b16 {%0,%1,%2,%3}, [%4];" \
                 : "=r"(r0), "=r"(r1), "=r"(r2), "=r"(r3) : "r"(addr))
#define MMA_TF32(c, a, b) \
    asm volatile("mma.sync.aligned.m16n8k8.row.col.f32.tf32.tf32.f32 " \
                 "{%0,%1,%2,%3},{%4,%5,%6,%7},{%8,%9},{%0,%1,%2,%3};" \
                 : "+f"((c)[0]), "+f"((c)[1]), "+f"((c)[2]), "+f"((c)[3]) \
                 : "r"((a)[0]), "r"((a)[1]), "r"((a)[2]), "r"((a)[3]), \
                   "r"((b)[0]), "r"((b)[1]))

__device__ __forceinline__ float tf32_rnd(float x) {
    uint32_t u = __float_as_uint(x), o;
    asm("cvt.rna.tf32.f32 %0, %1;" : "=r"(o) : "r"(u));
    return __uint_as_float(o);
}

// ------------------------- scratch (device globals) -------------------------
__device__ float g_xln[NN * FF];
__device__ float g_proj[NN * PF];      // [fh | ftl | fen] packed per row
__device__ float g_rln[RR * FF];
__device__ float g_fr [RR * FF];
__device__ int   g_cnt [NN];
__device__ int   g_fill[NN];
__device__ int   g_rowptr[NN + 1];
__device__ int   g_srcs[EE];
__device__ int   g_rids[EE];
__device__ float g_e[EE * HH];
__device__ float g_a[EE * HH];
__device__ float g_fa[NN * FF];
__device__ float g_fb[NN * FF];
__device__ float g_rst[NN * FF];
__device__ float g_y  [NN * FF];
__device__ float g_hid[NN * FHID];
__device__ float g_wcatT[PF * FF];     // K-major [768,256]: Whead|Wtail|Went rows
__device__ float g_wrelT [FF * FF];
__device__ float g_w1T[FHID * FF];
__device__ float g_w2T[FF * FHID];

// ------------------------- LayerNorm (outputs tf32-rounded) -------------------
__global__ void ln_kernel(const float* __restrict__ in, float* __restrict__ out,
                          const float* __restrict__ gam, const float* __restrict__ bet) {
    int row = blockIdx.x;
    int t = threadIdx.x;
    float x = in[row * FF + t];
    float s = x, s2 = x * x;
    #pragma unroll
    for (int o = 16; o; o >>= 1) {
        s  += __shfl_xor_sync(0xffffffffu, s,  o);
        s2 += __shfl_xor_sync(0xffffffffu, s2, o);
    }
    __shared__ float rs[8], rs2[8];
    int w = t >> 5, l = t & 31;
    if (l == 0) { rs[w] = s; rs2[w] = s2; }
    __syncthreads();
    s = 0.f; s2 = 0.f;
    #pragma unroll
    for (int i = 0; i < 8; i++) { s += rs[i]; s2 += rs2[i]; }
    float m = s * (1.0f / FF);
    float var = s2 * (1.0f / FF) - m * m;
    float inv = rsqrtf(var + 1e-5f);
    out[row * FF + t] = tf32_rnd((x - m) * inv * gam[t] + bet[t]);
}

// ------------------------- weight transpose (+tf32 round) --------------------
// generic: B (K x N) row-major -> BT (N x K) row-major
__global__ void transpose_rnd(const float* __restrict__ B, float* __restrict__ BT,
                              int K, int N) {
    __shared__ float t[32][33];
    int n0 = blockIdx.x * 32, k0 = blockIdx.y * 32;
    int x = threadIdx.x, y = threadIdx.y;
    #pragma unroll
    for (int r = 0; r < 32; r += 8)
        t[y + r][x] = B[(size_t)(k0 + y + r) * N + n0 + x];
    __syncthreads();
    #pragma unroll
    for (int r = 0; r < 32; r += 8)
        BT[(size_t)(n0 + y + r) * K + k0 + x] = tf32_rnd(t[x][y + r]);
}
// 4 square 256x256 weights in one launch: z<3 -> wcat rows z*256.., z=3 -> wrel
__global__ void transpose4_rnd(const float* __restrict__ Wh, const float* __restrict__ Wt,
                               const float* __restrict__ We, const float* __restrict__ Wr,
                               float* __restrict__ wcat, float* __restrict__ wrel) {
    __shared__ float t[32][33];
    int z = blockIdx.z;
    const float* B = (z == 0) ? Wh : (z == 1) ? Wt : (z == 2) ? We : Wr;
    float* BT = (z < 3) ? (wcat + (size_t)z * FF * FF) : wrel;
    int n0 = blockIdx.x * 32, k0 = blockIdx.y * 32;
    int x = threadIdx.x, y = threadIdx.y;
    #pragma unroll
    for (int r = 0; r < 32; r += 8)
        t[y + r][x] = B[(size_t)(k0 + y + r) * FF + n0 + x];
    __syncthreads();
    #pragma unroll
    for (int r = 0; r < 32; r += 8)
        BT[(size_t)(n0 + y + r) * FF + k0 + x] = tf32_rnd(t[x][y + r]);
}

// ------------------------- tf32 mma.sync GEMM --------------------------------
// C[M,Nc] = A[M,K] @ BT[Nc,K]^T (+bias) (relu if mode&1) (tf32-round if mode&2)
// (+res if res != null). 128x128 block tile, BK=32, 3-stage cp.async, 8 warps.
#define GSTAGES 3
#define GSTG 32768
#define GSMEM_BYTES (GSTAGES * GSTG)

__global__ void __launch_bounds__(256, 2)
mma_gemm(const float* __restrict__ A, const float* __restrict__ BT,
         float* __restrict__ C, int M, int Nc, int K,
         const float* __restrict__ bias, const float* __restrict__ res, int mode) {
    extern __shared__ float smemf[];
    const uint32_t sb = smem_u32(smemf);

    const int m0 = blockIdx.y * 128;
    const int n0 = blockIdx.x * 128;
    const int tid = threadIdx.x;
    const int warp = tid >> 5, lane = tid & 31;
    const int wm = warp >> 2, wn = warp & 3;          // 2 x 4 warps

    // ---- async load setup: each thread owns half a 128B row of A and B ----
    const int lrow = tid >> 1, lhalf = tid & 1;
    int aRow = m0 + lrow; if (aRow >= M) aRow = M - 1;
    const float* aG = A + (size_t)aRow * K + lhalf * 16;
    const float* bG = BT + (size_t)(n0 + lrow) * K + lhalf * 16;
    const uint32_t sA = sb + (uint32_t)lrow * 128;
    const uint32_t sB = sb + 16384 + (uint32_t)lrow * 128;
    uint32_t swz[4];
    #pragma unroll
    for (int j = 0; j < 4; j++)
        swz[j] = (uint32_t)(((lhalf * 4 + j) ^ (lrow & 7)) << 4);

    const int nCh = K >> 5;

    float c[4][4][4];
    #pragma unroll
    for (int mt = 0; mt < 4; mt++)
        #pragma unroll
        for (int nt = 0; nt < 4; nt++)
            #pragma unroll
            for (int q = 0; q < 4; q++) c[mt][nt][q] = 0.f;

    // prologue: stages 0 and 1
    #pragma unroll
    for (int s = 0; s < 2; s++) {
        const uint32_t off = (uint32_t)s * GSTG;
        const float* ag = aG + s * 32;
        const float* bg = bG + s * 32;
        #pragma unroll
        for (int j = 0; j < 4; j++) CP_ASYNC16(sA + off + swz[j], ag + j * 4);
        #pragma unroll
        for (int j = 0; j < 4; j++) CP_ASYNC16(sB + off + swz[j], bg + j * 4);
        CP_COMMIT();
    }

    const int q8 = lane >> 3, r8 = lane & 7;

    for (int i = 0; i < nCh; i++) {
        __syncthreads();                     // WAR: everyone done with stage (i+2)%3
        if (i + 2 < nCh) {
            const uint32_t off = (uint32_t)((i + 2) % GSTAGES) * GSTG;
            const float* ag = aG + (i + 2) * 32;
            const float* bg = bG + (i + 2) * 32;
            #pragma unroll
            for (int j = 0; j < 4; j++) CP_ASYNC16(sA + off + swz[j], ag + j * 4);
            #pragma unroll
            for (int j = 0; j < 4; j++) CP_ASYNC16(sB + off + swz[j], bg + j * 4);
        }
        CP_COMMIT();                          // constant group count per iter
        CP_WAIT(2);                           // chunk i resident
        __syncthreads();

        const uint32_t Ab = sb + (uint32_t)(i % GSTAGES) * GSTG;
        const uint32_t Bb = Ab + 16384;
        #pragma unroll
        for (int ks = 0; ks < 4; ks++) {
            uint32_t a[4][4];
            #pragma unroll
            for (int mt = 0; mt < 4; mt++) {
                const int rl = wm * 64 + mt * 16 + (q8 & 1) * 8 + r8;
                const int kc = ks * 2 + (q8 >> 1);
                const uint32_t ad = Ab + (uint32_t)rl * 128 + (uint32_t)((kc ^ (rl & 7)) << 4);
                LDSM_X4(a[mt][0], a[mt][1], a[mt][2], a[mt][3], ad);
            }
            uint32_t b[4][2];
            #pragma unroll
            for (int ntp = 0; ntp < 2; ntp++) {
                const int nl = wn * 32 + ntp * 16 + (q8 >> 1) * 8 + r8;
                const int kc = ks * 2 + (q8 & 1);
                const uint32_t bd = Bb + (uint32_t)nl * 128 + (uint32_t)((kc ^ (nl & 7)) << 4);
                LDSM_X4(b[ntp * 2][0], b[ntp * 2][1], b[ntp * 2 + 1][0], b[ntp * 2 + 1][1], bd);
            }
            #pragma unroll
            for (int mt = 0; mt < 4; mt++)
                #pragma unroll
                for (int nt = 0; nt < 4; nt++)
                    MMA_TF32(c[mt][nt], a[mt], b[nt]);
        }
    }

    // ---- epilogue ----
    const int g = lane >> 2, t4 = lane & 3;
    #pragma unroll
    for (int mt = 0; mt < 4; mt++) {
        #pragma unroll
        for (int half = 0; half < 2; half++) {
            const int m = m0 + wm * 64 + mt * 16 + g + half * 8;
            if (m < M) {
                float* cRow = C + (size_t)m * Nc + n0 + wn * 32;
                const float* rRow = res ? (res + (size_t)m * Nc + n0 + wn * 32) : nullptr;
                #pragma unroll
                for (int nt = 0; nt < 4; nt++) {
                    const int colb = nt * 8 + 2 * t4;
                    float v0 = c[mt][nt][half * 2 + 0];
                    float v1 = c[mt][nt][half * 2 + 1];
                    if (bias) {
                        const float* bp = bias + n0 + wn * 32 + colb;
                        v0 += bp[0]; v1 += bp[1];
                    }
                    if (mode & 1) { v0 = fmaxf(v0, 0.f); v1 = fmaxf(v1, 0.f); }
                    if (mode & 2) { v0 = tf32_rnd(v0); v1 = tf32_rnd(v1); }
                    if (rRow) { v0 += rRow[colb]; v1 += rRow[colb + 1]; }
                    float2 v; v.x = v0; v.y = v1;
                    *(float2*)(cRow + colb) = v;
                }
            }
        }
    }
}

// ------------------------- CSR build -----------------------------------------
__global__ void zero_kernel() {
    int i = blockIdx.x * blockDim.x + threadIdx.x;
    if (i < NN) { g_cnt[i] = 0; g_fill[i] = 0; }
}
__global__ void count_kernel(const int* __restrict__ dst) {
    int i = blockIdx.x * blockDim.x + threadIdx.x;
    if (i < EE) atomicAdd(&g_cnt[dst[i]], 1);
}
__global__ void scan_kernel() {
    __shared__ int ss[1024];
    int t = threadIdx.x;
    const int CH = (NN + 1023) / 1024;
    int base = t * CH;
    int loc = 0;
    for (int i = 0; i < CH; i++) {
        int idx = base + i;
        if (idx < NN) loc += g_cnt[idx];
    }
    ss[t] = loc;
    __syncthreads();
    for (int off = 1; off < 1024; off <<= 1) {
        int v = (t >= off) ? ss[t - off] : 0;
        __syncthreads();
        ss[t] += v;
        __syncthreads();
    }
    int run = (t == 0) ? 0 : ss[t - 1];
    for (int i = 0; i < CH; i++) {
        int idx = base + i;
        if (idx < NN) { g_rowptr[idx] = run; run += g_cnt[idx]; }
    }
    if (t == 0) g_rowptr[NN] = EE;
}
__global__ void scatter_kernel(const int* __restrict__ src, const int* __restrict__ dst,
                               const int* __restrict__ rid) {
    int i = blockIdx.x * blockDim.x + threadIdx.x;
    if (i < EE) {
        int d = dst[i];
        int pos = g_rowptr[d] + atomicAdd(&g_fill[d], 1);
        g_srcs[pos] = src[i];
        g_rids[pos] = rid[i];
    }
}

// ------------------------- edge attention + softmax ---------------------------
// one warp per dst node; fh/ftl live in g_proj (stride PF)
__global__ void attn_kernel(const float* __restrict__ attn) {
    int w = (blockIdx.x * blockDim.x + threadIdx.x) >> 5;
    int lane = threadIdx.x & 31;
    if (w >= NN) return;
    int node = w;
    float tl[HH], av[HH];
    #pragma unroll
    for (int h = 0; h < HH; h++) {
        tl[h] = g_proj[(size_t)node * PF + FF + h * DD + lane];
        av[h] = attn[h * DD + lane];
    }
    int beg = g_rowptr[node], end = g_rowptr[node + 1];
    float scale = logf((float)(end - beg)) * (1.0f / DD);
    for (int p = beg; p < end; p++) {
        int s = g_srcs[p], r = g_rids[p];
        const float* fhRow = g_proj + (size_t)s * PF;
        const float* frRow = g_fr + (size_t)r * FF;
        #pragma unroll
        for (int h = 0; h < HH; h++) {
            float x = fhRow[h * DD + lane] * tl[h] * frRow[h * DD + lane];
            x = (x > 0.f) ? x : SLOPE * x;
            float v = x * av[h];
            #pragma unroll
            for (int o = 16; o; o >>= 1) v += __shfl_xor_sync(0xffffffffu, v, o);
            if (lane == 0) g_e[p * HH + h] = v * scale;
        }
    }
    __syncwarp();
    if (lane < HH) {
        int h = lane;
        float m = -1e30f;
        for (int p = beg; p < end; p++) m = fmaxf(m, g_e[p * HH + h]);
        float ssum = 0.f;
        for (int p = beg; p < end; p++) ssum += expf(g_e[p * HH + h] - m);
        float inv = 1.0f / ssum;
        for (int p = beg; p < end; p++) g_a[p * HH + h] = expf(g_e[p * HH + h] - m) * inv;
    }
}

// ------------------------- diffusion hop --------------------------------------
// fout = (1-a)*agg + a*fen (+ent on last hop). fen is g_proj+512, stride PF.
__global__ void hop_kernel(const float* __restrict__ fin, int fstride,
                           float* __restrict__ fout, const float* __restrict__ ent) {
    int w = (blockIdx.x * blockDim.x + threadIdx.x) >> 5;
    int lane = threadIdx.x & 31;
    if (w >= NN) return;
    int node = w;
    int beg = g_rowptr[node], end = g_rowptr[node + 1];
    float acc[HH];
    #pragma unroll
    for (int h = 0; h < HH; h++) acc[h] = 0.f;
    for (int p = beg; p < end; p++) {
        int s = g_srcs[p];
        const float* frow = fin + (size_t)s * fstride;
        #pragma unroll
        for (int h = 0; h < HH; h++)
            acc[h] += g_a[p * HH + h] * frow[h * DD + lane];
    }
    const float* f0 = g_proj + (size_t)node * PF + 2 * FF;
    #pragma unroll
    for (int h = 0; h < HH; h++) {
        int cc = h * DD + lane;
        float v = (1.0f - ALPHA) * acc[h] + ALPHA * f0[cc];
        if (ent) v += ent[node * FF + cc];
        fout[(size_t)node * FF + cc] = v;
    }
}

// ------------------------- launcher -------------------------------------------
extern "C" void kernel_launch(void* const* d_in, const int* in_sizes, int n_in,
                              void* d_out, int out_size) {
    const float* ent_feat = (const float*)d_in[0];
    const float* rel_feat = (const float*)d_in[1];
    const float* W_head   = (const float*)d_in[2];
    const float* W_tail   = (const float*)d_in[3];
    const float* W_ent    = (const float*)d_in[4];
    const float* W_rel    = (const float*)d_in[5];
    const float* attn     = (const float*)d_in[6];
    const float* ln_ent_g = (const float*)d_in[7];
    const float* ln_ent_b = (const float*)d_in[8];
    const float* ln_rel_g = (const float*)d_in[9];
    const float* ln_rel_b = (const float*)d_in[10];
    const float* ln_ff_g  = (const float*)d_in[11];
    const float* ln_ff_b  = (const float*)d_in[12];
    const float* W1       = (const float*)d_in[13];
    const float* b1       = (const float*)d_in[14];
    const float* W2       = (const float*)d_in[15];
    const float* b2       = (const float*)d_in[16];
    const int*   src      = (const int*)d_in[17];
    const int*   dst      = (const int*)d_in[18];
    const int*   rid      = (const int*)d_in[19];
    float* out = (float*)d_out;

    cudaFuncSetAttribute(mma_gemm, cudaFuncAttributeMaxDynamicSharedMemorySize, GSMEM_BYTES);

    float *xln, *proj, *rln, *fr, *fa, *fb, *rst, *y, *hid, *wcat, *wrel, *w1T, *w2T;
    cudaGetSymbolAddress((void**)&xln,  g_xln);
    cudaGetSymbolAddress((void**)&proj, g_proj);
    cudaGetSymbolAddress((void**)&rln,  g_rln);
    cudaGetSymbolAddress((void**)&fr,   g_fr);
    cudaGetSymbolAddress((void**)&fa,   g_fa);
    cudaGetSymbolAddress((void**)&fb,   g_fb);
    cudaGetSymbolAddress((void**)&rst,  g_rst);
    cudaGetSymbolAddress((void**)&y,    g_y);
    cudaGetSymbolAddress((void**)&hid,  g_hid);
    cudaGetSymbolAddress((void**)&wcat, g_wcatT);
    cudaGetSymbolAddress((void**)&wrel, g_wrelT);
    cudaGetSymbolAddress((void**)&w1T,  g_w1T);
    cudaGetSymbolAddress((void**)&w2T,  g_w2T);

    // 0) transpose + tf32-round weights
    dim3 tb(32, 8);
    transpose4_rnd<<<dim3(FF / 32, FF / 32, 4), tb>>>(W_head, W_tail, W_ent, W_rel, wcat, wrel);
    transpose_rnd<<<dim3(FHID / 32, FF / 32), tb>>>(W1, w1T, FF, FHID);
    transpose_rnd<<<dim3(FF / 32, FHID / 32), tb>>>(W2, w2T, FHID, FF);

    // 1) LayerNorms (tf32-rounded outputs; only consumed by GEMMs)
    ln_kernel<<<NN, 256>>>(ent_feat, xln, ln_ent_g, ln_ent_b);
    ln_kernel<<<RR, 256>>>(rel_feat, rln, ln_rel_g, ln_rel_b);

    // 2) Projections: rel + fused head/tail/ent (Nc=768)
    const int mT = (NN + 127) / 128;   // 157
    mma_gemm<<<dim3(FF / 128, 1), 256, GSMEM_BYTES>>>(rln, wrel, fr, RR, FF, FF, nullptr, nullptr, 0);
    mma_gemm<<<dim3(PF / 128, mT), 256, GSMEM_BYTES>>>(xln, wcat, proj, NN, PF, FF, nullptr, nullptr, 0);

    // 3) CSR build (sorted by dst)
    zero_kernel<<<(NN + 255) / 256, 256>>>();
    count_kernel<<<(EE + 255) / 256, 256>>>(dst);
    scan_kernel<<<1, 1024>>>();
    scatter_kernel<<<(EE + 255) / 256, 256>>>(src, dst, rid);

    // 4) edge attention + per-node softmax
    attn_kernel<<<NN / 8, 256>>>(attn);

    // 5) 5 PPR hops (ping-pong), last adds ent_feat residual -> g_rst
    hop_kernel<<<NN / 8, 256>>>(proj + 2 * FF, PF, fa, nullptr);
    hop_kernel<<<NN / 8, 256>>>(fa, FF, fb, nullptr);
    hop_kernel<<<NN / 8, 256>>>(fb, FF, fa, nullptr);
    hop_kernel<<<NN / 8, 256>>>(fa, FF, fb, nullptr);
    hop_kernel<<<NN / 8, 256>>>(fb, FF, rst, ent_feat);

    // 6) FFN with pre-LN and residual
    ln_kernel<<<NN, 256>>>(rst, y, ln_ff_g, ln_ff_b);
    mma_gemm<<<dim3(FHID / 128, mT), 256, GSMEM_BYTES>>>(y, w1T, hid, NN, FHID, FF, b1, nullptr, 1 | 2);
    mma_gemm<<<dim3(FF / 128, mT), 256, GSMEM_BYTES>>>(hid, w2T, out, NN, FF, FHID, b2, rst, 0);
}